// round 6
// baseline (speedup 1.0000x reference)
#include <cuda_runtime.h>
#include <cuda_bf16.h>
#include <math.h>
#include <cstdint>

#define NWIN   1024
#define NT     64
#define DIMF   384
#define NHEADS 12
#define HDIM   32
#define MTOK   (NWIN * NT)          // 65536
#define QKVCOLS (3 * DIMF)          // 1152
#define KSPLIT  (3 * DIMF)          // 1152 = split-3 concatenated K
#define MAX_LOGIT 4.605170185988091f // ln(100)

#define BK      32
#define ASTRIDE 40                   // 32 + 8 pad (80 B/row, conflict-free ldmatrix)
#define STAGES  3
#define TILE_BYTES  (128 * ASTRIDE * 2)          // 10240 per operand tile
#define STAGE_BYTES (2 * TILE_BYTES)             // A + B
#define SMEM_DYN    (STAGES * STAGE_BYTES)       // 61440

// ---------------------------------------------------------------------------
// Scratch (device globals)
// ---------------------------------------------------------------------------
__device__ float         g_qkv[(size_t)MTOK * QKVCOLS];     // 302 MB
__device__ float         g_bias[NHEADS * NT * NT];
__device__ __nv_bfloat16 g_a[(size_t)MTOK * KSPLIT];        // 151 MB
__device__ __nv_bfloat16 g_wq[(size_t)QKVCOLS * KSPLIT];
__device__ __nv_bfloat16 g_wp[(size_t)DIMF * KSPLIT];

// ---------------------------------------------------------------------------
__device__ __forceinline__ uint32_t smem_u32(const void* p) {
    uint32_t a;
    asm("{ .reg .u64 t; cvta.to.shared.u64 t, %1; cvt.u32.u64 %0, t; }" : "=r"(a) : "l"(p));
    return a;
}
__device__ __forceinline__ void cp_async16(uint32_t saddr, const void* gaddr) {
    asm volatile("cp.async.cg.shared.global [%0], [%1], 16;" :: "r"(saddr), "l"(gaddr) : "memory");
}
__device__ __forceinline__ void ldm_x4(uint32_t& r0, uint32_t& r1, uint32_t& r2, uint32_t& r3,
                                       uint32_t addr) {
    asm volatile("ldmatrix.sync.aligned.m8n8.x4.shared.b16 {%0,%1,%2,%3}, [%4];"
                 : "=r"(r0), "=r"(r1), "=r"(r2), "=r"(r3) : "r"(addr));
}
__device__ __forceinline__ void mma16816(float& c0, float& c1, float& c2, float& c3,
                                         uint32_t a0, uint32_t a1, uint32_t a2, uint32_t a3,
                                         uint32_t b0, uint32_t b1) {
    asm volatile("mma.sync.aligned.m16n8k16.row.col.f32.bf16.bf16.f32 "
                 "{%0,%1,%2,%3}, {%4,%5,%6,%7}, {%8,%9}, {%0,%1,%2,%3};"
                 : "+f"(c0), "+f"(c1), "+f"(c2), "+f"(c3)
                 : "r"(a0), "r"(a1), "r"(a2), "r"(a3), "r"(b0), "r"(b1));
}

// ---------------------------------------------------------------------------
// K0: continuous position bias MLP + gather + 16*sigmoid
// ---------------------------------------------------------------------------
__global__ void rpb_kernel(const float* __restrict__ table,
                           const float* __restrict__ w1,
                           const float* __restrict__ b1,
                           const float* __restrict__ w2,
                           const float* __restrict__ b2,
                           const int*   __restrict__ idx)
{
    __shared__ float s_w1[1024];
    __shared__ float s_b1[512];
    __shared__ float s_w2[512 * 12];
    __shared__ float s_b2[12];
    __shared__ float s_rpb[225 * 12];
    int tid = threadIdx.x;

    for (int i = tid; i < 1024; i += 256) s_w1[i] = w1[i];
    for (int i = tid; i < 512;  i += 256) s_b1[i] = b1[i];
    for (int i = tid; i < 6144; i += 256) s_w2[i] = w2[i];
    if (tid < 12) s_b2[tid] = b2[tid];
    __syncthreads();

    if (tid < 225) {
        float t0 = table[tid * 2 + 0];
        float t1 = table[tid * 2 + 1];
        float acc[12];
        #pragma unroll
        for (int h = 0; h < 12; h++) acc[h] = s_b2[h];
        for (int j = 0; j < 512; j++) {
            float hj = fmaf(t0, s_w1[j], fmaf(t1, s_w1[512 + j], s_b1[j]));
            hj = fmaxf(hj, 0.0f);
            #pragma unroll
            for (int h = 0; h < 12; h++)
                acc[h] = fmaf(hj, s_w2[j * 12 + h], acc[h]);
        }
        #pragma unroll
        for (int h = 0; h < 12; h++) s_rpb[tid * 12 + h] = acc[h];
    }
    __syncthreads();

    for (int o = tid; o < NHEADS * NT * NT; o += 256) {
        int h = o >> 12;
        int p = o & 4095;
        float r = s_rpb[idx[p] * 12 + h];
        g_bias[o] = 16.0f / (1.0f + expf(-r));
    }
}

// ---------------------------------------------------------------------------
// Split fp32 activations [rows x 384] -> bf16 [rows x 1152] = [hi | hi | lo]
// ---------------------------------------------------------------------------
__global__ __launch_bounds__(256) void split_act(const float* __restrict__ in,
                                                 __nv_bfloat16* __restrict__ out)
{
    size_t t = (size_t)blockIdx.x * 256 + threadIdx.x;
    if (t >= (size_t)MTOK * 96) return;
    size_t m = t / 96;
    int c = (int)(t % 96) * 4;
    float4 v = *(const float4*)(in + m * DIMF + c);

    __nv_bfloat16 h0 = __float2bfloat16(v.x), h1 = __float2bfloat16(v.y);
    __nv_bfloat16 h2 = __float2bfloat16(v.z), h3 = __float2bfloat16(v.w);
    __nv_bfloat16 l0 = __float2bfloat16(v.x - __bfloat162float(h0));
    __nv_bfloat16 l1 = __float2bfloat16(v.y - __bfloat162float(h1));
    __nv_bfloat16 l2 = __float2bfloat16(v.z - __bfloat162float(h2));
    __nv_bfloat16 l3 = __float2bfloat16(v.w - __bfloat162float(h3));

    __nv_bfloat162 hp0 = __halves2bfloat162(h0, h1), hp1 = __halves2bfloat162(h2, h3);
    __nv_bfloat162 lp0 = __halves2bfloat162(l0, l1), lp1 = __halves2bfloat162(l2, l3);

    __nv_bfloat162* o0 = (__nv_bfloat162*)(out + m * KSPLIT + c);
    __nv_bfloat162* o1 = (__nv_bfloat162*)(out + m * KSPLIT + DIMF + c);
    __nv_bfloat162* o2 = (__nv_bfloat162*)(out + m * KSPLIT + 2 * DIMF + c);
    o0[0] = hp0; o0[1] = hp1;
    o1[0] = hp0; o1[1] = hp1;
    o2[0] = lp0; o2[1] = lp1;
}

// ---------------------------------------------------------------------------
// Split + transpose weights [384 x Ncols] -> bf16 [Ncols x 1152] = [hi|lo|hi]
// ---------------------------------------------------------------------------
__global__ __launch_bounds__(256) void split_w(const float* __restrict__ w,
                                               __nv_bfloat16* __restrict__ out, int Ncols)
{
    int t = blockIdx.x * 256 + threadIdx.x;
    if (t >= DIMF * Ncols) return;
    int k = t / Ncols, n = t % Ncols;
    float v = w[(size_t)k * Ncols + n];
    __nv_bfloat16 h = __float2bfloat16(v);
    __nv_bfloat16 l = __float2bfloat16(v - __bfloat162float(h));
    __nv_bfloat16* o = out + (size_t)n * KSPLIT;
    o[k] = h;
    o[DIMF + k] = l;
    o[2 * DIMF + k] = h;
}

// ---------------------------------------------------------------------------
// HMMA bf16 GEMM v2: C[M,N] = A'[M,K] @ B'[N,K]^T (+bias)
// 128 thr (4 warps), CTA tile 128x128, warp tile 64x64, BK=32, 3-stage ring,
// one __syncthreads per iteration. Dynamic smem = 61440 B.
// ---------------------------------------------------------------------------
__global__ __launch_bounds__(128) void gemm_hmma(
    const __nv_bfloat16* __restrict__ A, const __nv_bfloat16* __restrict__ B,
    const float* __restrict__ bias, float* __restrict__ C, int N, int K)
{
    extern __shared__ __align__(16) char dyn[];

    const int tid  = threadIdx.x;
    const int wid  = tid >> 5, lane = tid & 31;
    const int m0   = blockIdx.y * 128, n0 = blockIdx.x * 128;
    const int wm   = (wid & 1) * 64;
    const int wn   = (wid >> 1) * 64;
    const int KT   = K / BK;

    float c[4][8][4];
    #pragma unroll
    for (int i = 0; i < 4; i++)
        #pragma unroll
        for (int j = 0; j < 8; j++)
            #pragma unroll
            for (int l = 0; l < 4; l++) c[i][j][l] = 0.0f;

    // cp.async mapping: thread covers rows (tid>>2)+32t, 16B chunk (tid&3)
    const int arow = tid >> 2;       // 0..31
    const int aq   = tid & 3;        // 0..3
    const __nv_bfloat16* gA = A + (size_t)(m0 + arow) * K + aq * 8;
    const __nv_bfloat16* gB = B + (size_t)(n0 + arow) * K + aq * 8;

    const uint32_t sbase = smem_u32(dyn);
    uint32_t soff[4];
    #pragma unroll
    for (int t = 0; t < 4; t++)
        soff[t] = ((arow + 32 * t) * ASTRIDE + aq * 8) * 2;
    const size_t grow = (size_t)32 * K;   // 32-row stride in gmem

    // ldmatrix lane offsets
    const uint32_t a_off = ((wm + (lane & 15)) * ASTRIDE + (lane >> 4) * 8) * 2;
    const uint32_t b_off = ((wn + (lane & 7) + ((lane >> 4) << 3)) * ASTRIDE
                            + ((lane >> 3) & 1) * 8) * 2;

    // prologue: stages 0, 1
    #pragma unroll
    for (int s = 0; s < 2; s++) {
        const uint32_t sa = sbase + s * STAGE_BYTES;
        const uint32_t sb = sa + TILE_BYTES;
        const size_t ko = (size_t)s * BK;
        #pragma unroll
        for (int t = 0; t < 4; t++) {
            cp_async16(sa + soff[t], gA + t * grow + ko);
            cp_async16(sb + soff[t], gB + t * grow + ko);
        }
        asm volatile("cp.async.commit_group;" ::: "memory");
    }

    int stage = 0;
    for (int kt = 0; kt < KT; kt++) {
        if (kt < KT - 1) asm volatile("cp.async.wait_group 1;" ::: "memory");
        else             asm volatile("cp.async.wait_group 0;" ::: "memory");
        __syncthreads();   // publishes stage kt; all warps done with stage kt-1

        if (kt + 2 < KT) {
            int ns = stage + 2; if (ns >= STAGES) ns -= STAGES;
            const uint32_t sa = sbase + ns * STAGE_BYTES;
            const uint32_t sb = sa + TILE_BYTES;
            const size_t ko = (size_t)(kt + 2) * BK;
            #pragma unroll
            for (int t = 0; t < 4; t++) {
                cp_async16(sa + soff[t], gA + t * grow + ko);
                cp_async16(sb + soff[t], gB + t * grow + ko);
            }
            asm volatile("cp.async.commit_group;" ::: "memory");
        }

        const uint32_t aS = sbase + stage * STAGE_BYTES + a_off;
        const uint32_t bS = sbase + stage * STAGE_BYTES + TILE_BYTES + b_off;
        #pragma unroll
        for (int kk = 0; kk < 2; kk++) {
            uint32_t a[4][4];
            #pragma unroll
            for (int mi = 0; mi < 4; mi++)
                ldm_x4(a[mi][0], a[mi][1], a[mi][2], a[mi][3],
                       aS + (mi * 16 * ASTRIDE + kk * 16) * 2);
            uint32_t b[8][2];
            #pragma unroll
            for (int p = 0; p < 4; p++) {
                uint32_t r0, r1, r2, r3;
                ldm_x4(r0, r1, r2, r3, bS + (p * 16 * ASTRIDE + kk * 16) * 2);
                b[p * 2 + 0][0] = r0; b[p * 2 + 0][1] = r1;
                b[p * 2 + 1][0] = r2; b[p * 2 + 1][1] = r3;
            }
            #pragma unroll
            for (int mi = 0; mi < 4; mi++)
                #pragma unroll
                for (int ni = 0; ni < 8; ni++)
                    mma16816(c[mi][ni][0], c[mi][ni][1], c[mi][ni][2], c[mi][ni][3],
                             a[mi][0], a[mi][1], a[mi][2], a[mi][3],
                             b[ni][0], b[ni][1]);
        }
        stage++; if (stage >= STAGES) stage = 0;
    }

    // epilogue
    const int g = lane >> 2, tg = lane & 3;
    #pragma unroll
    for (int ni = 0; ni < 8; ni++) {
        const int col = n0 + wn + ni * 8 + tg * 2;
        float b0 = 0.0f, b1 = 0.0f;
        if (bias) { b0 = bias[col]; b1 = bias[col + 1]; }
        #pragma unroll
        for (int mi = 0; mi < 4; mi++) {
            const int row = m0 + wm + mi * 16 + g;
            float2 v0 = make_float2(c[mi][ni][0] + b0, c[mi][ni][1] + b1);
            float2 v1 = make_float2(c[mi][ni][2] + b0, c[mi][ni][3] + b1);
            *(float2*)(C + (size_t)row * N + col)       = v0;
            *(float2*)(C + (size_t)(row + 8) * N + col) = v1;
        }
    }
}

// ---------------------------------------------------------------------------
// K2: per (head, window) cosine attention, transposed smem layouts for LDS.128.
// Epilogue writes bf16 split [hi|hi|lo] directly to g_a (proj GEMM input).
// ---------------------------------------------------------------------------
__global__ __launch_bounds__(128) void attn_kernel(
    const float* __restrict__ mask, const float* __restrict__ logit_scale)
{
    const int h   = blockIdx.x;
    const int b   = blockIdx.y;
    const int tid = threadIdx.x;

    __shared__ float sqT[32][68];    // [k][token]
    __shared__ float skT[32][68];
    __shared__ float sv [64][36];    // [token][d]
    __shared__ float saT[64][68];    // [key][query]
    __shared__ float s_scale;

    const float* qkv = g_qkv + (size_t)b * 64 * QKVCOLS + h * 32;

    for (int i = tid; i < 512; i += 128) {
        int row = i >> 3;
        int f   = (i & 7) * 4;
        const float* base = qkv + (size_t)row * QKVCOLS + f;
        float4 v;
        v = *(const float4*)(base);
        sqT[f][row] = v.x; sqT[f + 1][row] = v.y; sqT[f + 2][row] = v.z; sqT[f + 3][row] = v.w;
        v = *(const float4*)(base + 384);
        skT[f][row] = v.x; skT[f + 1][row] = v.y; skT[f + 2][row] = v.z; skT[f + 3][row] = v.w;
        v = *(const float4*)(base + 768);
        *(float4*)&sv[row][f] = v;
    }
    if (tid == 0) s_scale = expf(fminf(logit_scale[h], MAX_LOGIT));
    __syncthreads();

    // normalize columns of sqT (with logit scale) / skT
    {
        int r = tid & 63;
        float (*mat)[68] = (tid < 64) ? sqT : skT;
        float ss = 0.0f;
        #pragma unroll
        for (int i = 0; i < 32; i++) { float v = mat[i][r]; ss = fmaf(v, v, ss); }
        float sc = rsqrtf(fmaxf(ss, 1e-12f));
        if (tid < 64) sc *= s_scale;
        #pragma unroll
        for (int i = 0; i < 32; i++) mat[i][r] *= sc;
    }
    __syncthreads();

    // scores: acc[4 q][8 k] per thread, all smem reads vectorized
    {
        const int r0 = (tid & 15) * 4, c0 = (tid >> 4) * 8;
        float acc[4][8];
        #pragma unroll
        for (int j = 0; j < 4; j++)
            #pragma unroll
            for (int l = 0; l < 8; l++) acc[j][l] = 0.0f;

        #pragma unroll
        for (int i = 0; i < 32; i++) {
            float4 aq = *(const float4*)&sqT[i][r0];
            float4 b0 = *(const float4*)&skT[i][c0];
            float4 b1 = *(const float4*)&skT[i][c0 + 4];
            float ar[4] = {aq.x, aq.y, aq.z, aq.w};
            float br[8] = {b0.x, b0.y, b0.z, b0.w, b1.x, b1.y, b1.z, b1.w};
            #pragma unroll
            for (int j = 0; j < 4; j++)
                #pragma unroll
                for (int l = 0; l < 8; l++)
                    acc[j][l] = fmaf(ar[j], br[l], acc[j][l]);
        }
        const float* mk = mask + (size_t)(b & 63) * 4096;
        const float* bi = g_bias + h * 4096;
        #pragma unroll
        for (int j = 0; j < 4; j++)
            #pragma unroll
            for (int l = 0; l < 8; l++) {
                int r = r0 + j, cc = c0 + l;
                saT[cc][r] = acc[j][l] + bi[r * 64 + cc] + mk[r * 64 + cc];
            }
    }
    __syncthreads();

    // softmax over key dim: thread tid<64 owns query row tid (column of saT)
    if (tid < 64) {
        float v[64];
        float m = -1e30f;
        #pragma unroll
        for (int cc = 0; cc < 64; cc++) { v[cc] = saT[cc][tid]; m = fmaxf(m, v[cc]); }
        float s0 = 0.f, s1 = 0.f, s2 = 0.f, s3 = 0.f;
        #pragma unroll
        for (int cc = 0; cc < 64; cc += 4) {
            v[cc + 0] = expf(v[cc + 0] - m); s0 += v[cc + 0];
            v[cc + 1] = expf(v[cc + 1] - m); s1 += v[cc + 1];
            v[cc + 2] = expf(v[cc + 2] - m); s2 += v[cc + 2];
            v[cc + 3] = expf(v[cc + 3] - m); s3 += v[cc + 3];
        }
        float inv = 1.0f / ((s0 + s1) + (s2 + s3));
        #pragma unroll
        for (int cc = 0; cc < 64; cc++) saT[cc][tid] = v[cc] * inv;
    }
    __syncthreads();

    // ctx = P @ V : acc[4 q][4 d]; write bf16 split [hi|hi|lo] into g_a
    {
        const int r0 = (tid & 15) * 4, d0 = (tid >> 4) * 4;
        float acc[4][4];
        #pragma unroll
        for (int j = 0; j < 4; j++)
            #pragma unroll
            for (int l = 0; l < 4; l++) acc[j][l] = 0.0f;

        #pragma unroll
        for (int cc = 0; cc < 64; cc++) {
            float4 ap = *(const float4*)&saT[cc][r0];
            float4 bv = *(const float4*)&sv[cc][d0];
            float pr[4] = {ap.x, ap.y, ap.z, ap.w};
            float vr[4] = {bv.x, bv.y, bv.z, bv.w};
            #pragma unroll
            for (int j = 0; j < 4; j++)
                #pragma unroll
                for (int l = 0; l < 4; l++)
                    acc[j][l] = fmaf(pr[j], vr[l], acc[j][l]);
        }

        const int col = h * 32 + d0;
        #pragma unroll
        for (int j = 0; j < 4; j++) {
            __nv_bfloat16 hi[4], lo[4];
            #pragma unroll
            for (int l = 0; l < 4; l++) {
                hi[l] = __float2bfloat16(acc[j][l]);
                lo[l] = __float2bfloat16(acc[j][l] - __bfloat162float(hi[l]));
            }
            __nv_bfloat162 hp0 = __halves2bfloat162(hi[0], hi[1]);
            __nv_bfloat162 hp1 = __halves2bfloat162(hi[2], hi[3]);
            __nv_bfloat162 lp0 = __halves2bfloat162(lo[0], lo[1]);
            __nv_bfloat162 lp1 = __halves2bfloat162(lo[2], lo[3]);
            __nv_bfloat16* o = g_a + (size_t)(b * 64 + r0 + j) * KSPLIT + col;
            ((__nv_bfloat162*)o)[0] = hp0;              ((__nv_bfloat162*)o)[1] = hp1;
            ((__nv_bfloat162*)(o + DIMF))[0] = hp0;     ((__nv_bfloat162*)(o + DIMF))[1] = hp1;
            ((__nv_bfloat162*)(o + 2 * DIMF))[0] = lp0; ((__nv_bfloat162*)(o + 2 * DIMF))[1] = lp1;
        }
    }
}

// ---------------------------------------------------------------------------
extern "C" void kernel_launch(void* const* d_in, const int* in_sizes, int n_in,
                              void* d_out, int out_size)
{
    const float* x           = (const float*)d_in[0];
    const float* mask        = (const float*)d_in[1];
    const float* qkv_w       = (const float*)d_in[2];
    const float* proj_w      = (const float*)d_in[3];
    const float* proj_b      = (const float*)d_in[4];
    const float* cpb_w1      = (const float*)d_in[5];
    const float* cpb_b1      = (const float*)d_in[6];
    const float* cpb_w2      = (const float*)d_in[7];
    const float* cpb_b2      = (const float*)d_in[8];
    const float* logit_scale = (const float*)d_in[9];
    const float* rpb_table   = (const float*)d_in[10];
    const int*   rpb_idx     = (const int*)d_in[11];
    float* out = (float*)d_out;

    float* qkv_ptr = nullptr;
    __nv_bfloat16 *a_ptr = nullptr, *wq_ptr = nullptr, *wp_ptr = nullptr;
    cudaGetSymbolAddress((void**)&qkv_ptr, g_qkv);
    cudaGetSymbolAddress((void**)&a_ptr,  g_a);
    cudaGetSymbolAddress((void**)&wq_ptr, g_wq);
    cudaGetSymbolAddress((void**)&wp_ptr, g_wp);

    static bool attr_set = false;
    if (!attr_set) {
        cudaFuncSetAttribute(gemm_hmma, cudaFuncAttributeMaxDynamicSharedMemorySize, SMEM_DYN);
        attr_set = true;
    }

    // K0: CPB bias table + weight splits (tiny)
    rpb_kernel<<<1, 256>>>(rpb_table, cpb_w1, cpb_b1, cpb_w2, cpb_b2, rpb_idx);
    split_w<<<(DIMF * QKVCOLS + 255) / 256, 256>>>(qkv_w, wq_ptr, QKVCOLS);
    split_w<<<(DIMF * DIMF + 255) / 256, 256>>>(proj_w, wp_ptr, DIMF);

    // split activations for QKV GEMM
    split_act<<<(int)(((size_t)MTOK * 96 + 255) / 256), 256>>>(x, a_ptr);

    // K1: QKV GEMM (65536 x 1152), K'=1152, HMMA
    gemm_hmma<<<dim3(QKVCOLS / 128, MTOK / 128), 128, SMEM_DYN>>>(
        a_ptr, wq_ptr, nullptr, qkv_ptr, QKVCOLS, KSPLIT);

    // K2: attention per (head, window); writes proj-input split into g_a
    attn_kernel<<<dim3(NHEADS, NWIN), 128>>>(mask, logit_scale);

    // K3: projection (65536 x 384) + bias, HMMA
    gemm_hmma<<<dim3(DIMF / 128, MTOK / 128), 128, SMEM_DYN>>>(
        a_ptr, wp_ptr, proj_b, out, DIMF, KSPLIT);
}

// round 9
// speedup vs baseline: 1.0262x; 1.0262x over previous
#include <cuda_runtime.h>
#include <cuda_bf16.h>
#include <math.h>
#include <cstdint>

#define NWIN   1024
#define NT     64
#define DIMF   384
#define NHEADS 12
#define HDIM   32
#define MTOK   (NWIN * NT)          // 65536
#define QKVCOLS (3 * DIMF)          // 1152
#define KSPLIT  (3 * DIMF)          // 1152 = split-3 concatenated K
#define MAX_LOGIT 4.605170185988091f // ln(100)

#define BK      32
#define ASTRIDE 40                   // 32 + 8 pad (80 bytes/row)

// ---------------------------------------------------------------------------
// Scratch (device globals)
// ---------------------------------------------------------------------------
__device__ float         g_qkv[(size_t)MTOK * QKVCOLS];     // 302 MB
__device__ float         g_bias[NHEADS * NT * NT];
__device__ __nv_bfloat16 g_a[(size_t)MTOK * KSPLIT];        // 151 MB
__device__ __nv_bfloat16 g_wq[(size_t)QKVCOLS * KSPLIT];
__device__ __nv_bfloat16 g_wp[(size_t)DIMF * KSPLIT];

// ---------------------------------------------------------------------------
__device__ __forceinline__ uint32_t smem_u32(const void* p) {
    uint32_t a;
    asm("{ .reg .u64 t; cvta.to.shared.u64 t, %1; cvt.u32.u64 %0, t; }" : "=r"(a) : "l"(p));
    return a;
}
__device__ __forceinline__ void cp_async16(uint32_t saddr, const void* gaddr) {
    asm volatile("cp.async.cg.shared.global [%0], [%1], 16;" :: "r"(saddr), "l"(gaddr) : "memory");
}
__device__ __forceinline__ void ldm_x4(uint32_t& r0, uint32_t& r1, uint32_t& r2, uint32_t& r3,
                                       uint32_t addr) {
    asm volatile("ldmatrix.sync.aligned.m8n8.x4.shared.b16 {%0,%1,%2,%3}, [%4];"
                 : "=r"(r0), "=r"(r1), "=r"(r2), "=r"(r3) : "r"(addr));
}
__device__ __forceinline__ void mma16816(float& c0, float& c1, float& c2, float& c3,
                                         uint32_t a0, uint32_t a1, uint32_t a2, uint32_t a3,
                                         uint32_t b0, uint32_t b1) {
    asm volatile("mma.sync.aligned.m16n8k16.row.col.f32.bf16.bf16.f32 "
                 "{%0,%1,%2,%3}, {%4,%5,%6,%7}, {%8,%9}, {%0,%1,%2,%3};"
                 : "+f"(c0), "+f"(c1), "+f"(c2), "+f"(c3)
                 : "r"(a0), "r"(a1), "r"(a2), "r"(a3), "r"(b0), "r"(b1));
}

// ---------------------------------------------------------------------------
// K0: continuous position bias MLP + gather + 16*sigmoid
// ---------------------------------------------------------------------------
__global__ void rpb_kernel(const float* __restrict__ table,
                           const float* __restrict__ w1,
                           const float* __restrict__ b1,
                           const float* __restrict__ w2,
                           const float* __restrict__ b2,
                           const int*   __restrict__ idx)
{
    __shared__ float s_w1[1024];
    __shared__ float s_b1[512];
    __shared__ float s_w2[512 * 12];
    __shared__ float s_b2[12];
    __shared__ float s_rpb[225 * 12];
    int tid = threadIdx.x;

    for (int i = tid; i < 1024; i += 256) s_w1[i] = w1[i];
    for (int i = tid; i < 512;  i += 256) s_b1[i] = b1[i];
    for (int i = tid; i < 6144; i += 256) s_w2[i] = w2[i];
    if (tid < 12) s_b2[tid] = b2[tid];
    __syncthreads();

    if (tid < 225) {
        float t0 = table[tid * 2 + 0];
        float t1 = table[tid * 2 + 1];
        float acc[12];
        #pragma unroll
        for (int h = 0; h < 12; h++) acc[h] = s_b2[h];
        for (int j = 0; j < 512; j++) {
            float hj = fmaf(t0, s_w1[j], fmaf(t1, s_w1[512 + j], s_b1[j]));
            hj = fmaxf(hj, 0.0f);
            #pragma unroll
            for (int h = 0; h < 12; h++)
                acc[h] = fmaf(hj, s_w2[j * 12 + h], acc[h]);
        }
        #pragma unroll
        for (int h = 0; h < 12; h++) s_rpb[tid * 12 + h] = acc[h];
    }
    __syncthreads();

    for (int o = tid; o < NHEADS * NT * NT; o += 256) {
        int h = o >> 12;
        int p = o & 4095;
        float r = s_rpb[idx[p] * 12 + h];
        g_bias[o] = 16.0f / (1.0f + expf(-r));
    }
}

// ---------------------------------------------------------------------------
// Split fp32 activations [rows x 384] -> bf16 [rows x 1152] = [hi | hi | lo]
// ---------------------------------------------------------------------------
__global__ __launch_bounds__(256) void split_act(const float* __restrict__ in,
                                                 __nv_bfloat16* __restrict__ out)
{
    size_t t = (size_t)blockIdx.x * 256 + threadIdx.x;
    if (t >= (size_t)MTOK * 96) return;
    size_t m = t / 96;
    int c = (int)(t % 96) * 4;
    float4 v = *(const float4*)(in + m * DIMF + c);

    __nv_bfloat16 h0 = __float2bfloat16(v.x), h1 = __float2bfloat16(v.y);
    __nv_bfloat16 h2 = __float2bfloat16(v.z), h3 = __float2bfloat16(v.w);
    __nv_bfloat16 l0 = __float2bfloat16(v.x - __bfloat162float(h0));
    __nv_bfloat16 l1 = __float2bfloat16(v.y - __bfloat162float(h1));
    __nv_bfloat16 l2 = __float2bfloat16(v.z - __bfloat162float(h2));
    __nv_bfloat16 l3 = __float2bfloat16(v.w - __bfloat162float(h3));

    __nv_bfloat162 hp0 = __halves2bfloat162(h0, h1), hp1 = __halves2bfloat162(h2, h3);
    __nv_bfloat162 lp0 = __halves2bfloat162(l0, l1), lp1 = __halves2bfloat162(l2, l3);

    __nv_bfloat162* o0 = (__nv_bfloat162*)(out + m * KSPLIT + c);
    __nv_bfloat162* o1 = (__nv_bfloat162*)(out + m * KSPLIT + DIMF + c);
    __nv_bfloat162* o2 = (__nv_bfloat162*)(out + m * KSPLIT + 2 * DIMF + c);
    o0[0] = hp0; o0[1] = hp1;
    o1[0] = hp0; o1[1] = hp1;
    o2[0] = lp0; o2[1] = lp1;
}

// ---------------------------------------------------------------------------
// Split + transpose weights [384 x Ncols] -> bf16 [Ncols x 1152] = [hi|lo|hi]
// ---------------------------------------------------------------------------
__global__ __launch_bounds__(256) void split_w(const float* __restrict__ w,
                                               __nv_bfloat16* __restrict__ out, int Ncols)
{
    int t = blockIdx.x * 256 + threadIdx.x;
    if (t >= DIMF * Ncols) return;
    int k = t / Ncols, n = t % Ncols;
    float v = w[(size_t)k * Ncols + n];
    __nv_bfloat16 h = __float2bfloat16(v);
    __nv_bfloat16 l = __float2bfloat16(v - __bfloat162float(h));
    __nv_bfloat16* o = out + (size_t)n * KSPLIT;
    o[k] = h;
    o[DIMF + k] = l;
    o[2 * DIMF + k] = h;
}

// ---------------------------------------------------------------------------
// HMMA bf16 GEMM (R5-proven): C[M,N] = A'[M,K] @ B'[N,K]^T (+bias)
// CTA: 256 thr, tile 128x128xBK(32), double-buffered cp.async.
// Warp tile 64(M)x32(N): wm = (wid&1)*64, wn = (wid>>1)*32.
// ---------------------------------------------------------------------------
__global__ __launch_bounds__(256) void gemm_hmma(
    const __nv_bfloat16* __restrict__ A, const __nv_bfloat16* __restrict__ B,
    const float* __restrict__ bias, float* __restrict__ C, int N, int K)
{
    __shared__ __nv_bfloat16 sA[2][128 * ASTRIDE];
    __shared__ __nv_bfloat16 sB[2][128 * ASTRIDE];

    const int tid  = threadIdx.x;
    const int wid  = tid >> 5, lane = tid & 31;
    const int m0   = blockIdx.y * 128, n0 = blockIdx.x * 128;
    const int wm   = (wid & 1) * 64;
    const int wn   = (wid >> 1) * 32;
    const int KT   = K / BK;

    float c[4][4][4];
    #pragma unroll
    for (int i = 0; i < 4; i++)
        #pragma unroll
        for (int j = 0; j < 4; j++)
            #pragma unroll
            for (int l = 0; l < 4; l++) c[i][j][l] = 0.0f;

    const int lrow = tid >> 2;        // 0..63
    const int lq   = tid & 3;         // 0..3
    const __nv_bfloat16* gA0 = A + (size_t)(m0 + lrow)      * K + lq * 8;
    const __nv_bfloat16* gA1 = A + (size_t)(m0 + lrow + 64) * K + lq * 8;
    const __nv_bfloat16* gB0 = B + (size_t)(n0 + lrow)      * K + lq * 8;
    const __nv_bfloat16* gB1 = B + (size_t)(n0 + lrow + 64) * K + lq * 8;

    uint32_t sA_st[2], sB_st[2], sA_base[2], sB_base[2];
    #pragma unroll
    for (int s = 0; s < 2; s++) {
        sA_base[s] = smem_u32(&sA[s][0]);
        sB_base[s] = smem_u32(&sB[s][0]);
        sA_st[s] = sA_base[s] + (lrow * ASTRIDE + lq * 8) * 2;
        sB_st[s] = sB_base[s] + (lrow * ASTRIDE + lq * 8) * 2;
    }
    const uint32_t rowoff = 64 * ASTRIDE * 2;

    const uint32_t a_off = ((wm + (lane & 15)) * ASTRIDE + (lane >> 4) * 8) * 2;
    const uint32_t b_off = ((wn + (lane & 7) + ((lane >> 4) << 3)) * ASTRIDE
                            + ((lane >> 3) & 1) * 8) * 2;

    {
        cp_async16(sA_st[0],          gA0);
        cp_async16(sA_st[0] + rowoff, gA1);
        cp_async16(sB_st[0],          gB0);
        cp_async16(sB_st[0] + rowoff, gB1);
        asm volatile("cp.async.commit_group;" ::: "memory");
    }

    for (int kt = 0; kt < KT; kt++) {
        const int cur = kt & 1;
        if (kt + 1 < KT) {
            const int nxt = cur ^ 1;
            const size_t ko = (size_t)(kt + 1) * BK;
            cp_async16(sA_st[nxt],          gA0 + ko);
            cp_async16(sA_st[nxt] + rowoff, gA1 + ko);
            cp_async16(sB_st[nxt],          gB0 + ko);
            cp_async16(sB_st[nxt] + rowoff, gB1 + ko);
            asm volatile("cp.async.commit_group;" ::: "memory");
            asm volatile("cp.async.wait_group 1;" ::: "memory");
        } else {
            asm volatile("cp.async.wait_group 0;" ::: "memory");
        }
        __syncthreads();

        const uint32_t aS = sA_base[cur] + a_off;
        const uint32_t bS = sB_base[cur] + b_off;
        #pragma unroll
        for (int kk = 0; kk < 2; kk++) {
            uint32_t a[4][4];
            #pragma unroll
            for (int mi = 0; mi < 4; mi++)
                ldm_x4(a[mi][0], a[mi][1], a[mi][2], a[mi][3],
                       aS + (mi * 16 * ASTRIDE + kk * 16) * 2);
            uint32_t b[4][2];
            #pragma unroll
            for (int p = 0; p < 2; p++) {
                uint32_t r0, r1, r2, r3;
                ldm_x4(r0, r1, r2, r3, bS + (p * 16 * ASTRIDE + kk * 16) * 2);
                b[p * 2 + 0][0] = r0; b[p * 2 + 0][1] = r1;
                b[p * 2 + 1][0] = r2; b[p * 2 + 1][1] = r3;
            }
            #pragma unroll
            for (int mi = 0; mi < 4; mi++)
                #pragma unroll
                for (int ni = 0; ni < 4; ni++)
                    mma16816(c[mi][ni][0], c[mi][ni][1], c[mi][ni][2], c[mi][ni][3],
                             a[mi][0], a[mi][1], a[mi][2], a[mi][3],
                             b[ni][0], b[ni][1]);
        }
        __syncthreads();
    }

    const int g = lane >> 2, tg = lane & 3;
    #pragma unroll
    for (int ni = 0; ni < 4; ni++) {
        const int col = n0 + wn + ni * 8 + tg * 2;
        float b0 = 0.0f, b1 = 0.0f;
        if (bias) { b0 = bias[col]; b1 = bias[col + 1]; }
        #pragma unroll
        for (int mi = 0; mi < 4; mi++) {
            const int row = m0 + wm + mi * 16 + g;
            float2 v0 = make_float2(c[mi][ni][0] + b0, c[mi][ni][1] + b1);
            float2 v1 = make_float2(c[mi][ni][2] + b0, c[mi][ni][3] + b1);
            *(float2*)(C + (size_t)row * N + col)       = v0;
            *(float2*)(C + (size_t)(row + 8) * N + col) = v1;
        }
    }
}

// ---------------------------------------------------------------------------
// K2: per (head, window) cosine attention, LDS.128 inner loops.
// Epilogue writes bf16 split [hi|hi|lo] directly to g_a (proj GEMM input).
// ---------------------------------------------------------------------------
__global__ __launch_bounds__(128) void attn_kernel(
    const float* __restrict__ mask, const float* __restrict__ logit_scale)
{
    const int h   = blockIdx.x;
    const int b   = blockIdx.y;
    const int tid = threadIdx.x;

    __shared__ float sqT[32][68];    // [k][token]
    __shared__ float skT[32][68];
    __shared__ float sv [64][36];    // [token][d]
    __shared__ float saT[64][68];    // [key][query]
    __shared__ float s_scale;

    const float* qkv = g_qkv + (size_t)b * 64 * QKVCOLS + h * 32;

    for (int i = tid; i < 512; i += 128) {
        int row = i >> 3;
        int f   = (i & 7) * 4;
        const float* base = qkv + (size_t)row * QKVCOLS + f;
        float4 v;
        v = *(const float4*)(base);
        sqT[f][row] = v.x; sqT[f + 1][row] = v.y; sqT[f + 2][row] = v.z; sqT[f + 3][row] = v.w;
        v = *(const float4*)(base + 384);
        skT[f][row] = v.x; skT[f + 1][row] = v.y; skT[f + 2][row] = v.z; skT[f + 3][row] = v.w;
        v = *(const float4*)(base + 768);
        *(float4*)&sv[row][f] = v;
    }
    if (tid == 0) s_scale = expf(fminf(logit_scale[h], MAX_LOGIT));
    __syncthreads();

    // normalize columns of sqT (with logit scale) / skT
    {
        int r = tid & 63;
        float (*mat)[68] = (tid < 64) ? sqT : skT;
        float ss = 0.0f;
        #pragma unroll
        for (int i = 0; i < 32; i++) { float v = mat[i][r]; ss = fmaf(v, v, ss); }
        float sc = rsqrtf(fmaxf(ss, 1e-12f));
        if (tid < 64) sc *= s_scale;
        #pragma unroll
        for (int i = 0; i < 32; i++) mat[i][r] *= sc;
    }
    __syncthreads();

    // scores: acc[4 q][8 k] per thread, vectorized smem reads
    {
        const int r0 = (tid & 15) * 4, c0 = (tid >> 4) * 8;
        float acc[4][8];
        #pragma unroll
        for (int j = 0; j < 4; j++)
            #pragma unroll
            for (int l = 0; l < 8; l++) acc[j][l] = 0.0f;

        #pragma unroll
        for (int i = 0; i < 32; i++) {
            float4 aq = *(const float4*)&sqT[i][r0];
            float4 b0 = *(const float4*)&skT[i][c0];
            float4 b1 = *(const float4*)&skT[i][c0 + 4];
            float ar[4] = {aq.x, aq.y, aq.z, aq.w};
            float br[8] = {b0.x, b0.y, b0.z, b0.w, b1.x, b1.y, b1.z, b1.w};
            #pragma unroll
            for (int j = 0; j < 4; j++)
                #pragma unroll
                for (int l = 0; l < 8; l++)
                    acc[j][l] = fmaf(ar[j], br[l], acc[j][l]);
        }
        const float* mk = mask + (size_t)(b & 63) * 4096;
        const float* bi = g_bias + h * 4096;
        #pragma unroll
        for (int j = 0; j < 4; j++)
            #pragma unroll
            for (int l = 0; l < 8; l++) {
                int r = r0 + j, cc = c0 + l;
                saT[cc][r] = acc[j][l] + bi[r * 64 + cc] + mk[r * 64 + cc];
            }
    }
    __syncthreads();

    // softmax over key dim: thread tid<64 owns query row tid (column of saT)
    if (tid < 64) {
        float v[64];
        float m = -1e30f;
        #pragma unroll
        for (int cc = 0; cc < 64; cc++) { v[cc] = saT[cc][tid]; m = fmaxf(m, v[cc]); }
        float s0 = 0.f, s1 = 0.f, s2 = 0.f, s3 = 0.f;
        #pragma unroll
        for (int cc = 0; cc < 64; cc += 4) {
            v[cc + 0] = expf(v[cc + 0] - m); s0 += v[cc + 0];
            v[cc + 1] = expf(v[cc + 1] - m); s1 += v[cc + 1];
            v[cc + 2] = expf(v[cc + 2] - m); s2 += v[cc + 2];
            v[cc + 3] = expf(v[cc + 3] - m); s3 += v[cc + 3];
        }
        float inv = 1.0f / ((s0 + s1) + (s2 + s3));
        #pragma unroll
        for (int cc = 0; cc < 64; cc++) saT[cc][tid] = v[cc] * inv;
    }
    __syncthreads();

    // ctx = P @ V : acc[4 q][4 d]; write bf16 split [hi|hi|lo] into g_a
    {
        const int r0 = (tid & 15) * 4, d0 = (tid >> 4) * 4;
        float acc[4][4];
        #pragma unroll
        for (int j = 0; j < 4; j++)
            #pragma unroll
            for (int l = 0; l < 4; l++) acc[j][l] = 0.0f;

        #pragma unroll
        for (int cc = 0; cc < 64; cc++) {
            float4 ap = *(const float4*)&saT[cc][r0];
            float4 bv = *(const float4*)&sv[cc][d0];
            float pr[4] = {ap.x, ap.y, ap.z, ap.w};
            float vr[4] = {bv.x, bv.y, bv.z, bv.w};
            #pragma unroll
            for (int j = 0; j < 4; j++)
                #pragma unroll
                for (int l = 0; l < 4; l++)
                    acc[j][l] = fmaf(pr[j], vr[l], acc[j][l]);
        }

        const int col = h * 32 + d0;
        #pragma unroll
        for (int j = 0; j < 4; j++) {
            __nv_bfloat16 hi[4], lo[4];
            #pragma unroll
            for (int l = 0; l < 4; l++) {
                hi[l] = __float2bfloat16(acc[j][l]);
                lo[l] = __float2bfloat16(acc[j][l] - __bfloat162float(hi[l]));
            }
            __nv_bfloat162 hp0 = __halves2bfloat162(hi[0], hi[1]);
            __nv_bfloat162 hp1 = __halves2bfloat162(hi[2], hi[3]);
            __nv_bfloat162 lp0 = __halves2bfloat162(lo[0], lo[1]);
            __nv_bfloat162 lp1 = __halves2bfloat162(lo[2], lo[3]);
            __nv_bfloat16* o = g_a + (size_t)(b * 64 + r0 + j) * KSPLIT + col;
            ((__nv_bfloat162*)o)[0] = hp0;              ((__nv_bfloat162*)o)[1] = hp1;
            ((__nv_bfloat162*)(o + DIMF))[0] = hp0;     ((__nv_bfloat162*)(o + DIMF))[1] = hp1;
            ((__nv_bfloat162*)(o + 2 * DIMF))[0] = lp0; ((__nv_bfloat162*)(o + 2 * DIMF))[1] = lp1;
        }
    }
}

// ---------------------------------------------------------------------------
extern "C" void kernel_launch(void* const* d_in, const int* in_sizes, int n_in,
                              void* d_out, int out_size)
{
    const float* x           = (const float*)d_in[0];
    const float* mask        = (const float*)d_in[1];
    const float* qkv_w       = (const float*)d_in[2];
    const float* proj_w      = (const float*)d_in[3];
    const float* proj_b      = (const float*)d_in[4];
    const float* cpb_w1      = (const float*)d_in[5];
    const float* cpb_b1      = (const float*)d_in[6];
    const float* cpb_w2      = (const float*)d_in[7];
    const float* cpb_b2      = (const float*)d_in[8];
    const float* logit_scale = (const float*)d_in[9];
    const float* rpb_table   = (const float*)d_in[10];
    const int*   rpb_idx     = (const int*)d_in[11];
    float* out = (float*)d_out;

    float* qkv_ptr = nullptr;
    __nv_bfloat16 *a_ptr = nullptr, *wq_ptr = nullptr, *wp_ptr = nullptr;
    cudaGetSymbolAddress((void**)&qkv_ptr, g_qkv);
    cudaGetSymbolAddress((void**)&a_ptr,  g_a);
    cudaGetSymbolAddress((void**)&wq_ptr, g_wq);
    cudaGetSymbolAddress((void**)&wp_ptr, g_wp);

    // K0: CPB bias table + weight splits (tiny)
    rpb_kernel<<<1, 256>>>(rpb_table, cpb_w1, cpb_b1, cpb_w2, cpb_b2, rpb_idx);
    split_w<<<(DIMF * QKVCOLS + 255) / 256, 256>>>(qkv_w, wq_ptr, QKVCOLS);
    split_w<<<(DIMF * DIMF + 255) / 256, 256>>>(proj_w, wp_ptr, DIMF);

    // split activations for QKV GEMM
    split_act<<<(int)(((size_t)MTOK * 96 + 255) / 256), 256>>>(x, a_ptr);

    // K1: QKV GEMM (65536 x 1152), K'=1152, HMMA
    gemm_hmma<<<dim3(QKVCOLS / 128, MTOK / 128), 256>>>(
        a_ptr, wq_ptr, nullptr, qkv_ptr, QKVCOLS, KSPLIT);

    // K2: attention per (head, window); writes proj-input split into g_a
    attn_kernel<<<dim3(NHEADS, NWIN), 128>>>(mask, logit_scale);

    // K3: projection (65536 x 384) + bias, HMMA
    gemm_hmma<<<dim3(DIMF / 128, MTOK / 128), 256>>>(
        a_ptr, wp_ptr, proj_b, out, DIMF, KSPLIT);
}

// round 10
// speedup vs baseline: 1.7170x; 1.6732x over previous
#include <cuda_runtime.h>
#include <cuda_fp16.h>
#include <math.h>
#include <cstdint>

#define NWIN   1024
#define NT     64
#define DIMF   384
#define NHEADS 12
#define HDIM   32
#define MTOK   (NWIN * NT)          // 65536
#define QKVCOLS (3 * DIMF)          // 1152
#define MAX_LOGIT 4.605170185988091f // ln(100)

#define BK      32
#define ASTRIDE 40                   // 32 + 8 pad (80 bytes/row)

// ---------------------------------------------------------------------------
// Scratch (device globals)
// ---------------------------------------------------------------------------
__device__ float  g_qkv[(size_t)MTOK * QKVCOLS];   // 302 MB
__device__ float  g_bias[NHEADS * NT * NT];
__device__ __half g_a[(size_t)MTOK * DIMF];        // 50 MB (fp16 acts, reused)
__device__ __half g_wq[(size_t)QKVCOLS * DIMF];    // [N][K] fp16
__device__ __half g_wp[(size_t)DIMF * DIMF];

// ---------------------------------------------------------------------------
__device__ __forceinline__ uint32_t smem_u32(const void* p) {
    uint32_t a;
    asm("{ .reg .u64 t; cvta.to.shared.u64 t, %1; cvt.u32.u64 %0, t; }" : "=r"(a) : "l"(p));
    return a;
}
__device__ __forceinline__ void cp_async16(uint32_t saddr, const void* gaddr) {
    asm volatile("cp.async.cg.shared.global [%0], [%1], 16;" :: "r"(saddr), "l"(gaddr) : "memory");
}
__device__ __forceinline__ void ldm_x4(uint32_t& r0, uint32_t& r1, uint32_t& r2, uint32_t& r3,
                                       uint32_t addr) {
    asm volatile("ldmatrix.sync.aligned.m8n8.x4.shared.b16 {%0,%1,%2,%3}, [%4];"
                 : "=r"(r0), "=r"(r1), "=r"(r2), "=r"(r3) : "r"(addr));
}
__device__ __forceinline__ void mma16816(float& c0, float& c1, float& c2, float& c3,
                                         uint32_t a0, uint32_t a1, uint32_t a2, uint32_t a3,
                                         uint32_t b0, uint32_t b1) {
    asm volatile("mma.sync.aligned.m16n8k16.row.col.f32.f16.f16.f32 "
                 "{%0,%1,%2,%3}, {%4,%5,%6,%7}, {%8,%9}, {%0,%1,%2,%3};"
                 : "+f"(c0), "+f"(c1), "+f"(c2), "+f"(c3)
                 : "r"(a0), "r"(a1), "r"(a2), "r"(a3), "r"(b0), "r"(b1));
}

// ---------------------------------------------------------------------------
// K0: continuous position bias MLP + gather + 16*sigmoid
// ---------------------------------------------------------------------------
__global__ void rpb_kernel(const float* __restrict__ table,
                           const float* __restrict__ w1,
                           const float* __restrict__ b1,
                           const float* __restrict__ w2,
                           const float* __restrict__ b2,
                           const int*   __restrict__ idx)
{
    __shared__ float s_w1[1024];
    __shared__ float s_b1[512];
    __shared__ float s_w2[512 * 12];
    __shared__ float s_b2[12];
    __shared__ float s_rpb[225 * 12];
    int tid = threadIdx.x;

    for (int i = tid; i < 1024; i += 256) s_w1[i] = w1[i];
    for (int i = tid; i < 512;  i += 256) s_b1[i] = b1[i];
    for (int i = tid; i < 6144; i += 256) s_w2[i] = w2[i];
    if (tid < 12) s_b2[tid] = b2[tid];
    __syncthreads();

    if (tid < 225) {
        float t0 = table[tid * 2 + 0];
        float t1 = table[tid * 2 + 1];
        float acc[12];
        #pragma unroll
        for (int h = 0; h < 12; h++) acc[h] = s_b2[h];
        for (int j = 0; j < 512; j++) {
            float hj = fmaf(t0, s_w1[j], fmaf(t1, s_w1[512 + j], s_b1[j]));
            hj = fmaxf(hj, 0.0f);
            #pragma unroll
            for (int h = 0; h < 12; h++)
                acc[h] = fmaf(hj, s_w2[j * 12 + h], acc[h]);
        }
        #pragma unroll
        for (int h = 0; h < 12; h++) s_rpb[tid * 12 + h] = acc[h];
    }
    __syncthreads();

    for (int o = tid; o < NHEADS * NT * NT; o += 256) {
        int h = o >> 12;
        int p = o & 4095;
        float r = s_rpb[idx[p] * 12 + h];
        g_bias[o] = 16.0f / (1.0f + expf(-r));
    }
}

// ---------------------------------------------------------------------------
// Convert fp32 activations [rows x 384] -> fp16 [rows x 384]
// ---------------------------------------------------------------------------
__global__ __launch_bounds__(256) void conv_act(const float* __restrict__ in,
                                                __half* __restrict__ out)
{
    size_t t = (size_t)blockIdx.x * 256 + threadIdx.x;   // over MTOK*96 float4s
    if (t >= (size_t)MTOK * 96) return;
    float4 v = *(const float4*)(in + t * 4);
    __half2 p0 = __floats2half2_rn(v.x, v.y);
    __half2 p1 = __floats2half2_rn(v.z, v.w);
    __half2* o = (__half2*)(out + t * 4);
    o[0] = p0; o[1] = p1;
}

// ---------------------------------------------------------------------------
// Convert + transpose weights [384 x Ncols] fp32 -> fp16 [Ncols x 384]
// ---------------------------------------------------------------------------
__global__ __launch_bounds__(256) void conv_w(const float* __restrict__ w,
                                              __half* __restrict__ out, int Ncols)
{
    int t = blockIdx.x * 256 + threadIdx.x;
    if (t >= DIMF * Ncols) return;
    int k = t / Ncols, n = t % Ncols;               // coalesced read
    out[(size_t)n * DIMF + k] = __float2half(w[(size_t)k * Ncols + n]);
}

// ---------------------------------------------------------------------------
// HMMA fp16 GEMM (R5-proven config): C[M,N] = A[M,K] @ B[N,K]^T (+bias)
// CTA: 256 thr, tile 128x128xBK(32), double-buffered cp.async.
// Warp tile 64(M)x32(N): wm = (wid&1)*64, wn = (wid>>1)*32.
// ---------------------------------------------------------------------------
__global__ __launch_bounds__(256) void gemm_hmma(
    const __half* __restrict__ A, const __half* __restrict__ B,
    const float* __restrict__ bias, float* __restrict__ C, int N, int K)
{
    __shared__ __half sA[2][128 * ASTRIDE];
    __shared__ __half sB[2][128 * ASTRIDE];

    const int tid  = threadIdx.x;
    const int wid  = tid >> 5, lane = tid & 31;
    const int m0   = blockIdx.y * 128, n0 = blockIdx.x * 128;
    const int wm   = (wid & 1) * 64;
    const int wn   = (wid >> 1) * 32;
    const int KT   = K / BK;

    float c[4][4][4];
    #pragma unroll
    for (int i = 0; i < 4; i++)
        #pragma unroll
        for (int j = 0; j < 4; j++)
            #pragma unroll
            for (int l = 0; l < 4; l++) c[i][j][l] = 0.0f;

    const int lrow = tid >> 2;        // 0..63
    const int lq   = tid & 3;         // 0..3
    const __half* gA0 = A + (size_t)(m0 + lrow)      * K + lq * 8;
    const __half* gA1 = A + (size_t)(m0 + lrow + 64) * K + lq * 8;
    const __half* gB0 = B + (size_t)(n0 + lrow)      * K + lq * 8;
    const __half* gB1 = B + (size_t)(n0 + lrow + 64) * K + lq * 8;

    uint32_t sA_st[2], sB_st[2], sA_base[2], sB_base[2];
    #pragma unroll
    for (int s = 0; s < 2; s++) {
        sA_base[s] = smem_u32(&sA[s][0]);
        sB_base[s] = smem_u32(&sB[s][0]);
        sA_st[s] = sA_base[s] + (lrow * ASTRIDE + lq * 8) * 2;
        sB_st[s] = sB_base[s] + (lrow * ASTRIDE + lq * 8) * 2;
    }
    const uint32_t rowoff = 64 * ASTRIDE * 2;

    const uint32_t a_off = ((wm + (lane & 15)) * ASTRIDE + (lane >> 4) * 8) * 2;
    const uint32_t b_off = ((wn + (lane & 7) + ((lane >> 4) << 3)) * ASTRIDE
                            + ((lane >> 3) & 1) * 8) * 2;

    {
        cp_async16(sA_st[0],          gA0);
        cp_async16(sA_st[0] + rowoff, gA1);
        cp_async16(sB_st[0],          gB0);
        cp_async16(sB_st[0] + rowoff, gB1);
        asm volatile("cp.async.commit_group;" ::: "memory");
    }

    for (int kt = 0; kt < KT; kt++) {
        const int cur = kt & 1;
        if (kt + 1 < KT) {
            const int nxt = cur ^ 1;
            const size_t ko = (size_t)(kt + 1) * BK;
            cp_async16(sA_st[nxt],          gA0 + ko);
            cp_async16(sA_st[nxt] + rowoff, gA1 + ko);
            cp_async16(sB_st[nxt],          gB0 + ko);
            cp_async16(sB_st[nxt] + rowoff, gB1 + ko);
            asm volatile("cp.async.commit_group;" ::: "memory");
            asm volatile("cp.async.wait_group 1;" ::: "memory");
        } else {
            asm volatile("cp.async.wait_group 0;" ::: "memory");
        }
        __syncthreads();

        const uint32_t aS = sA_base[cur] + a_off;
        const uint32_t bS = sB_base[cur] + b_off;
        #pragma unroll
        for (int kk = 0; kk < 2; kk++) {
            uint32_t a[4][4];
            #pragma unroll
            for (int mi = 0; mi < 4; mi++)
                ldm_x4(a[mi][0], a[mi][1], a[mi][2], a[mi][3],
                       aS + (mi * 16 * ASTRIDE + kk * 16) * 2);
            uint32_t b[4][2];
            #pragma unroll
            for (int p = 0; p < 2; p++) {
                uint32_t r0, r1, r2, r3;
                ldm_x4(r0, r1, r2, r3, bS + (p * 16 * ASTRIDE + kk * 16) * 2);
                b[p * 2 + 0][0] = r0; b[p * 2 + 0][1] = r1;
                b[p * 2 + 1][0] = r2; b[p * 2 + 1][1] = r3;
            }
            #pragma unroll
            for (int mi = 0; mi < 4; mi++)
                #pragma unroll
                for (int ni = 0; ni < 4; ni++)
                    mma16816(c[mi][ni][0], c[mi][ni][1], c[mi][ni][2], c[mi][ni][3],
                             a[mi][0], a[mi][1], a[mi][2], a[mi][3],
                             b[ni][0], b[ni][1]);
        }
        __syncthreads();
    }

    const int g = lane >> 2, tg = lane & 3;
    #pragma unroll
    for (int ni = 0; ni < 4; ni++) {
        const int col = n0 + wn + ni * 8 + tg * 2;
        float b0 = 0.0f, b1 = 0.0f;
        if (bias) { b0 = bias[col]; b1 = bias[col + 1]; }
        #pragma unroll
        for (int mi = 0; mi < 4; mi++) {
            const int row = m0 + wm + mi * 16 + g;
            float2 v0 = make_float2(c[mi][ni][0] + b0, c[mi][ni][1] + b1);
            float2 v1 = make_float2(c[mi][ni][2] + b0, c[mi][ni][3] + b1);
            *(float2*)(C + (size_t)row * N + col)       = v0;
            *(float2*)(C + (size_t)(row + 8) * N + col) = v1;
        }
    }
}

// ---------------------------------------------------------------------------
// K2: per (head, window) cosine attention, LDS.128 inner loops.
// Epilogue writes fp16 ctx directly to g_a (proj GEMM input).
// ---------------------------------------------------------------------------
__global__ __launch_bounds__(128) void attn_kernel(
    const float* __restrict__ mask, const float* __restrict__ logit_scale)
{
    const int h   = blockIdx.x;
    const int b   = blockIdx.y;
    const int tid = threadIdx.x;

    __shared__ float sqT[32][68];    // [k][token]
    __shared__ float skT[32][68];
    __shared__ float sv [64][36];    // [token][d]
    __shared__ float saT[64][68];    // [key][query]
    __shared__ float s_scale;

    const float* qkv = g_qkv + (size_t)b * 64 * QKVCOLS + h * 32;

    for (int i = tid; i < 512; i += 128) {
        int row = i >> 3;
        int f   = (i & 7) * 4;
        const float* base = qkv + (size_t)row * QKVCOLS + f;
        float4 v;
        v = *(const float4*)(base);
        sqT[f][row] = v.x; sqT[f + 1][row] = v.y; sqT[f + 2][row] = v.z; sqT[f + 3][row] = v.w;
        v = *(const float4*)(base + 384);
        skT[f][row] = v.x; skT[f + 1][row] = v.y; skT[f + 2][row] = v.z; skT[f + 3][row] = v.w;
        v = *(const float4*)(base + 768);
        *(float4*)&sv[row][f] = v;
    }
    if (tid == 0) s_scale = expf(fminf(logit_scale[h], MAX_LOGIT));
    __syncthreads();

    // normalize columns of sqT (with logit scale) / skT
    {
        int r = tid & 63;
        float (*mat)[68] = (tid < 64) ? sqT : skT;
        float ss = 0.0f;
        #pragma unroll
        for (int i = 0; i < 32; i++) { float v = mat[i][r]; ss = fmaf(v, v, ss); }
        float sc = rsqrtf(fmaxf(ss, 1e-12f));
        if (tid < 64) sc *= s_scale;
        #pragma unroll
        for (int i = 0; i < 32; i++) mat[i][r] *= sc;
    }
    __syncthreads();

    // scores: acc[4 q][8 k] per thread, vectorized smem reads
    {
        const int r0 = (tid & 15) * 4, c0 = (tid >> 4) * 8;
        float acc[4][8];
        #pragma unroll
        for (int j = 0; j < 4; j++)
            #pragma unroll
            for (int l = 0; l < 8; l++) acc[j][l] = 0.0f;

        #pragma unroll
        for (int i = 0; i < 32; i++) {
            float4 aq = *(const float4*)&sqT[i][r0];
            float4 b0 = *(const float4*)&skT[i][c0];
            float4 b1 = *(const float4*)&skT[i][c0 + 4];
            float ar[4] = {aq.x, aq.y, aq.z, aq.w};
            float br[8] = {b0.x, b0.y, b0.z, b0.w, b1.x, b1.y, b1.z, b1.w};
            #pragma unroll
            for (int j = 0; j < 4; j++)
                #pragma unroll
                for (int l = 0; l < 8; l++)
                    acc[j][l] = fmaf(ar[j], br[l], acc[j][l]);
        }
        const float* mk = mask + (size_t)(b & 63) * 4096;
        const float* bi = g_bias + h * 4096;
        #pragma unroll
        for (int j = 0; j < 4; j++)
            #pragma unroll
            for (int l = 0; l < 8; l++) {
                int r = r0 + j, cc = c0 + l;
                saT[cc][r] = acc[j][l] + bi[r * 64 + cc] + mk[r * 64 + cc];
            }
    }
    __syncthreads();

    // softmax over key dim: thread tid<64 owns query row tid (column of saT)
    if (tid < 64) {
        float v[64];
        float m = -1e30f;
        #pragma unroll
        for (int cc = 0; cc < 64; cc++) { v[cc] = saT[cc][tid]; m = fmaxf(m, v[cc]); }
        float s0 = 0.f, s1 = 0.f, s2 = 0.f, s3 = 0.f;
        #pragma unroll
        for (int cc = 0; cc < 64; cc += 4) {
            v[cc + 0] = expf(v[cc + 0] - m); s0 += v[cc + 0];
            v[cc + 1] = expf(v[cc + 1] - m); s1 += v[cc + 1];
            v[cc + 2] = expf(v[cc + 2] - m); s2 += v[cc + 2];
            v[cc + 3] = expf(v[cc + 3] - m); s3 += v[cc + 3];
        }
        float inv = 1.0f / ((s0 + s1) + (s2 + s3));
        #pragma unroll
        for (int cc = 0; cc < 64; cc++) saT[cc][tid] = v[cc] * inv;
    }
    __syncthreads();

    // ctx = P @ V : acc[4 q][4 d]; write fp16 into g_a
    {
        const int r0 = (tid & 15) * 4, d0 = (tid >> 4) * 4;
        float acc[4][4];
        #pragma unroll
        for (int j = 0; j < 4; j++)
            #pragma unroll
            for (int l = 0; l < 4; l++) acc[j][l] = 0.0f;

        #pragma unroll
        for (int cc = 0; cc < 64; cc++) {
            float4 ap = *(const float4*)&saT[cc][r0];
            float4 bv = *(const float4*)&sv[cc][d0];
            float pr[4] = {ap.x, ap.y, ap.z, ap.w};
            float vr[4] = {bv.x, bv.y, bv.z, bv.w};
            #pragma unroll
            for (int j = 0; j < 4; j++)
                #pragma unroll
                for (int l = 0; l < 4; l++)
                    acc[j][l] = fmaf(pr[j], vr[l], acc[j][l]);
        }

        const int col = h * 32 + d0;
        #pragma unroll
        for (int j = 0; j < 4; j++) {
            __half2 p0 = __floats2half2_rn(acc[j][0], acc[j][1]);
            __half2 p1 = __floats2half2_rn(acc[j][2], acc[j][3]);
            __half2* o = (__half2*)(g_a + (size_t)(b * 64 + r0 + j) * DIMF + col);
            o[0] = p0; o[1] = p1;
        }
    }
}

// ---------------------------------------------------------------------------
extern "C" void kernel_launch(void* const* d_in, const int* in_sizes, int n_in,
                              void* d_out, int out_size)
{
    const float* x           = (const float*)d_in[0];
    const float* mask        = (const float*)d_in[1];
    const float* qkv_w       = (const float*)d_in[2];
    const float* proj_w      = (const float*)d_in[3];
    const float* proj_b      = (const float*)d_in[4];
    const float* cpb_w1      = (const float*)d_in[5];
    const float* cpb_b1      = (const float*)d_in[6];
    const float* cpb_w2      = (const float*)d_in[7];
    const float* cpb_b2      = (const float*)d_in[8];
    const float* logit_scale = (const float*)d_in[9];
    const float* rpb_table   = (const float*)d_in[10];
    const int*   rpb_idx     = (const int*)d_in[11];
    float* out = (float*)d_out;

    float* qkv_ptr = nullptr;
    __half *a_ptr = nullptr, *wq_ptr = nullptr, *wp_ptr = nullptr;
    cudaGetSymbolAddress((void**)&qkv_ptr, g_qkv);
    cudaGetSymbolAddress((void**)&a_ptr,  g_a);
    cudaGetSymbolAddress((void**)&wq_ptr, g_wq);
    cudaGetSymbolAddress((void**)&wp_ptr, g_wp);

    // K0: CPB bias table + weight converts (tiny)
    rpb_kernel<<<1, 256>>>(rpb_table, cpb_w1, cpb_b1, cpb_w2, cpb_b2, rpb_idx);
    conv_w<<<(DIMF * QKVCOLS + 255) / 256, 256>>>(qkv_w, wq_ptr, QKVCOLS);
    conv_w<<<(DIMF * DIMF + 255) / 256, 256>>>(proj_w, wp_ptr, DIMF);

    // convert activations for QKV GEMM
    conv_act<<<(int)(((size_t)MTOK * 96 + 255) / 256), 256>>>(x, a_ptr);

    // K1: QKV GEMM (65536 x 1152 x 384), fp16 HMMA
    gemm_hmma<<<dim3(QKVCOLS / 128, MTOK / 128), 256>>>(
        a_ptr, wq_ptr, nullptr, qkv_ptr, QKVCOLS, DIMF);

    // K2: attention per (head, window); writes fp16 ctx into g_a
    attn_kernel<<<dim3(NHEADS, NWIN), 128>>>(mask, logit_scale);

    // K3: projection (65536 x 384 x 384) + bias, fp16 HMMA
    gemm_hmma<<<dim3(DIMF / 128, MTOK / 128), 256>>>(
        a_ptr, wp_ptr, proj_b, out, DIMF, DIMF);
}

// round 12
// speedup vs baseline: 2.4172x; 1.4078x over previous
#include <cuda_runtime.h>
#include <cuda_fp16.h>
#include <cuda_bf16.h>
#include <math.h>
#include <cstdint>

#define NWIN   1024
#define NT     64
#define DIMF   384
#define NHEADS 12
#define HDIM   32
#define MTOK   (NWIN * NT)          // 65536
#define QKVCOLS (3 * DIMF)          // 1152
#define MAX_LOGIT 4.605170185988091f // ln(100)

#define BK      32
#define ASTRIDE 40                   // 32 + 8 pad (80 bytes/row, 16B-multiple)
#define VSTRIDE 72                   // 64 + 8 pad (144 bytes/row, 16B-multiple)

// ---------------------------------------------------------------------------
// Scratch (device globals)
// ---------------------------------------------------------------------------
__device__ float  g_qkv[(size_t)MTOK * QKVCOLS];   // 302 MB
__device__ float  g_bias[NHEADS * NT * NT];
__device__ float  g_bm[(size_t)NHEADS * 64 * NT * NT]; // bias+mask combined, 12.6 MB
__device__ __half g_a[(size_t)MTOK * DIMF];        // 50 MB (fp16 acts, reused)
__device__ __half g_wq[(size_t)QKVCOLS * DIMF];    // [N][K] fp16
__device__ __half g_wp[(size_t)DIMF * DIMF];

// ---------------------------------------------------------------------------
__device__ __forceinline__ uint32_t smem_u32(const void* p) {
    uint32_t a;
    asm("{ .reg .u64 t; cvta.to.shared.u64 t, %1; cvt.u32.u64 %0, t; }" : "=r"(a) : "l"(p));
    return a;
}
__device__ __forceinline__ void cp_async16(uint32_t saddr, const void* gaddr) {
    asm volatile("cp.async.cg.shared.global [%0], [%1], 16;" :: "r"(saddr), "l"(gaddr) : "memory");
}
__device__ __forceinline__ void ldm_x4(uint32_t& r0, uint32_t& r1, uint32_t& r2, uint32_t& r3,
                                       uint32_t addr) {
    asm volatile("ldmatrix.sync.aligned.m8n8.x4.shared.b16 {%0,%1,%2,%3}, [%4];"
                 : "=r"(r0), "=r"(r1), "=r"(r2), "=r"(r3) : "r"(addr));
}
__device__ __forceinline__ void mma16816(float& c0, float& c1, float& c2, float& c3,
                                         uint32_t a0, uint32_t a1, uint32_t a2, uint32_t a3,
                                         uint32_t b0, uint32_t b1) {
    asm volatile("mma.sync.aligned.m16n8k16.row.col.f32.f16.f16.f32 "
                 "{%0,%1,%2,%3}, {%4,%5,%6,%7}, {%8,%9}, {%0,%1,%2,%3};"
                 : "+f"(c0), "+f"(c1), "+f"(c2), "+f"(c3)
                 : "r"(a0), "r"(a1), "r"(a2), "r"(a3), "r"(b0), "r"(b1));
}
__device__ __forceinline__ void mma16816bf(float* c,
                                           const uint32_t* a,
                                           uint32_t b0, uint32_t b1) {
    asm volatile("mma.sync.aligned.m16n8k16.row.col.f32.bf16.bf16.f32 "
                 "{%0,%1,%2,%3}, {%4,%5,%6,%7}, {%8,%9}, {%0,%1,%2,%3};"
                 : "+f"(c[0]), "+f"(c[1]), "+f"(c[2]), "+f"(c[3])
                 : "r"(a[0]), "r"(a[1]), "r"(a[2]), "r"(a[3]), "r"(b0), "r"(b1));
}
// split float pair into packed bf16 hi and lo words
__device__ __forceinline__ void splitpack(float x, float y, uint32_t& hi, uint32_t& lo) {
    __nv_bfloat16 hx = __float2bfloat16(x), hy = __float2bfloat16(y);
    __nv_bfloat162 h2; h2.x = hx; h2.y = hy;
    hi = *(uint32_t*)&h2;
    __nv_bfloat16 lx = __float2bfloat16(x - __bfloat162float(hx));
    __nv_bfloat16 ly = __float2bfloat16(y - __bfloat162float(hy));
    __nv_bfloat162 l2; l2.x = lx; l2.y = ly;
    lo = *(uint32_t*)&l2;
}

// ---------------------------------------------------------------------------
// K0: continuous position bias MLP + gather + 16*sigmoid
// ---------------------------------------------------------------------------
__global__ void rpb_kernel(const float* __restrict__ table,
                           const float* __restrict__ w1,
                           const float* __restrict__ b1,
                           const float* __restrict__ w2,
                           const float* __restrict__ b2,
                           const int*   __restrict__ idx)
{
    __shared__ float s_w1[1024];
    __shared__ float s_b1[512];
    __shared__ float s_w2[512 * 12];
    __shared__ float s_b2[12];
    __shared__ float s_rpb[225 * 12];
    int tid = threadIdx.x;

    for (int i = tid; i < 1024; i += 256) s_w1[i] = w1[i];
    for (int i = tid; i < 512;  i += 256) s_b1[i] = b1[i];
    for (int i = tid; i < 6144; i += 256) s_w2[i] = w2[i];
    if (tid < 12) s_b2[tid] = b2[tid];
    __syncthreads();

    if (tid < 225) {
        float t0 = table[tid * 2 + 0];
        float t1 = table[tid * 2 + 1];
        float acc[12];
        #pragma unroll
        for (int h = 0; h < 12; h++) acc[h] = s_b2[h];
        for (int j = 0; j < 512; j++) {
            float hj = fmaf(t0, s_w1[j], fmaf(t1, s_w1[512 + j], s_b1[j]));
            hj = fmaxf(hj, 0.0f);
            #pragma unroll
            for (int h = 0; h < 12; h++)
                acc[h] = fmaf(hj, s_w2[j * 12 + h], acc[h]);
        }
        #pragma unroll
        for (int h = 0; h < 12; h++) s_rpb[tid * 12 + h] = acc[h];
    }
    __syncthreads();

    for (int o = tid; o < NHEADS * NT * NT; o += 256) {
        int h = o >> 12;
        int p = o & 4095;
        float r = s_rpb[idx[p] * 12 + h];
        g_bias[o] = 16.0f / (1.0f + expf(-r));
    }
}

// combine bias (per head) + mask (per window group) into one table
__global__ __launch_bounds__(256) void bm_kernel(const float* __restrict__ mask)
{
    int hw = blockIdx.x;                 // 0..767 = h*64 + w
    const float* bi = g_bias + (hw >> 6) * 4096;
    const float* mk = mask + (size_t)(hw & 63) * 4096;
    float* o = g_bm + (size_t)hw * 4096;
    for (int i = threadIdx.x; i < 4096; i += 256) o[i] = bi[i] + mk[i];
}

// ---------------------------------------------------------------------------
// Convert fp32 activations -> fp16
// ---------------------------------------------------------------------------
__global__ __launch_bounds__(256) void conv_act(const float* __restrict__ in,
                                                __half* __restrict__ out)
{
    size_t t = (size_t)blockIdx.x * 256 + threadIdx.x;
    if (t >= (size_t)MTOK * 96) return;
    float4 v = *(const float4*)(in + t * 4);
    __half2 p0 = __floats2half2_rn(v.x, v.y);
    __half2 p1 = __floats2half2_rn(v.z, v.w);
    __half2* o = (__half2*)(out + t * 4);
    o[0] = p0; o[1] = p1;
}

// Convert + transpose weights [384 x Ncols] fp32 -> fp16 [Ncols x 384]
__global__ __launch_bounds__(256) void conv_w(const float* __restrict__ w,
                                              __half* __restrict__ out, int Ncols)
{
    int t = blockIdx.x * 256 + threadIdx.x;
    if (t >= DIMF * Ncols) return;
    int k = t / Ncols, n = t % Ncols;
    out[(size_t)n * DIMF + k] = __float2half(w[(size_t)k * Ncols + n]);
}

// ---------------------------------------------------------------------------
// HMMA fp16 GEMM (R5-proven config): C[M,N] = A[M,K] @ B[N,K]^T (+bias)
// ---------------------------------------------------------------------------
__global__ __launch_bounds__(256) void gemm_hmma(
    const __half* __restrict__ A, const __half* __restrict__ B,
    const float* __restrict__ bias, float* __restrict__ C, int N, int K)
{
    __shared__ alignas(16) __half sA[2][128 * ASTRIDE];
    __shared__ alignas(16) __half sB[2][128 * ASTRIDE];

    const int tid  = threadIdx.x;
    const int wid  = tid >> 5, lane = tid & 31;
    const int m0   = blockIdx.y * 128, n0 = blockIdx.x * 128;
    const int wm   = (wid & 1) * 64;
    const int wn   = (wid >> 1) * 32;
    const int KT   = K / BK;

    float c[4][4][4];
    #pragma unroll
    for (int i = 0; i < 4; i++)
        #pragma unroll
        for (int j = 0; j < 4; j++)
            #pragma unroll
            for (int l = 0; l < 4; l++) c[i][j][l] = 0.0f;

    const int lrow = tid >> 2;
    const int lq   = tid & 3;
    const __half* gA0 = A + (size_t)(m0 + lrow)      * K + lq * 8;
    const __half* gA1 = A + (size_t)(m0 + lrow + 64) * K + lq * 8;
    const __half* gB0 = B + (size_t)(n0 + lrow)      * K + lq * 8;
    const __half* gB1 = B + (size_t)(n0 + lrow + 64) * K + lq * 8;

    uint32_t sA_st[2], sB_st[2], sA_base[2], sB_base[2];
    #pragma unroll
    for (int s = 0; s < 2; s++) {
        sA_base[s] = smem_u32(&sA[s][0]);
        sB_base[s] = smem_u32(&sB[s][0]);
        sA_st[s] = sA_base[s] + (lrow * ASTRIDE + lq * 8) * 2;
        sB_st[s] = sB_base[s] + (lrow * ASTRIDE + lq * 8) * 2;
    }
    const uint32_t rowoff = 64 * ASTRIDE * 2;

    const uint32_t a_off = ((wm + (lane & 15)) * ASTRIDE + (lane >> 4) * 8) * 2;
    const uint32_t b_off = ((wn + (lane & 7) + ((lane >> 4) << 3)) * ASTRIDE
                            + ((lane >> 3) & 1) * 8) * 2;

    {
        cp_async16(sA_st[0],          gA0);
        cp_async16(sA_st[0] + rowoff, gA1);
        cp_async16(sB_st[0],          gB0);
        cp_async16(sB_st[0] + rowoff, gB1);
        asm volatile("cp.async.commit_group;" ::: "memory");
    }

    for (int kt = 0; kt < KT; kt++) {
        const int cur = kt & 1;
        if (kt + 1 < KT) {
            const int nxt = cur ^ 1;
            const size_t ko = (size_t)(kt + 1) * BK;
            cp_async16(sA_st[nxt],          gA0 + ko);
            cp_async16(sA_st[nxt] + rowoff, gA1 + ko);
            cp_async16(sB_st[nxt],          gB0 + ko);
            cp_async16(sB_st[nxt] + rowoff, gB1 + ko);
            asm volatile("cp.async.commit_group;" ::: "memory");
            asm volatile("cp.async.wait_group 1;" ::: "memory");
        } else {
            asm volatile("cp.async.wait_group 0;" ::: "memory");
        }
        __syncthreads();

        const uint32_t aS = sA_base[cur] + a_off;
        const uint32_t bS = sB_base[cur] + b_off;
        #pragma unroll
        for (int kk = 0; kk < 2; kk++) {
            uint32_t a[4][4];
            #pragma unroll
            for (int mi = 0; mi < 4; mi++)
                ldm_x4(a[mi][0], a[mi][1], a[mi][2], a[mi][3],
                       aS + (mi * 16 * ASTRIDE + kk * 16) * 2);
            uint32_t b[4][2];
            #pragma unroll
            for (int p = 0; p < 2; p++) {
                uint32_t r0, r1, r2, r3;
                ldm_x4(r0, r1, r2, r3, bS + (p * 16 * ASTRIDE + kk * 16) * 2);
                b[p * 2 + 0][0] = r0; b[p * 2 + 0][1] = r1;
                b[p * 2 + 1][0] = r2; b[p * 2 + 1][1] = r3;
            }
            #pragma unroll
            for (int mi = 0; mi < 4; mi++)
                #pragma unroll
                for (int ni = 0; ni < 4; ni++)
                    mma16816(c[mi][ni][0], c[mi][ni][1], c[mi][ni][2], c[mi][ni][3],
                             a[mi][0], a[mi][1], a[mi][2], a[mi][3],
                             b[ni][0], b[ni][1]);
        }
        __syncthreads();
    }

    const int g = lane >> 2, tg = lane & 3;
    #pragma unroll
    for (int ni = 0; ni < 4; ni++) {
        const int col = n0 + wn + ni * 8 + tg * 2;
        float b0 = 0.0f, b1 = 0.0f;
        if (bias) { b0 = bias[col]; b1 = bias[col + 1]; }
        #pragma unroll
        for (int mi = 0; mi < 4; mi++) {
            const int row = m0 + wm + mi * 16 + g;
            float2 v0 = make_float2(c[mi][ni][0] + b0, c[mi][ni][1] + b1);
            float2 v1 = make_float2(c[mi][ni][2] + b0, c[mi][ni][3] + b1);
            *(float2*)(C + (size_t)row * N + col)       = v0;
            *(float2*)(C + (size_t)(row + 8) * N + col) = v1;
        }
    }
}

// ---------------------------------------------------------------------------
// K2: attention via split-2 bf16 tensor-core MMA. One CTA per (head, window).
// 4 warps; warp w owns 16 query rows (wm = w*16).
// scores = (qh+ql)(kh+kl)^T ~ qh*kh + qh*kl + ql*kh   (fp32 accum)
// softmax in fragments (fp32, __expf, shfl reductions)
// ctx    = (ph+pl)(vh+vl)   ~ ph*vh + ph*vl + pl*vh,  P never leaves registers
// ---------------------------------------------------------------------------
__global__ __launch_bounds__(128) void attn_kernel(const float* __restrict__ lscale)
{
    const int h   = blockIdx.x;
    const int b   = blockIdx.y;
    const int tid = threadIdx.x;
    const int wid = tid >> 5, lane = tid & 31;
    const int g   = lane >> 2, tg = lane & 3;
    const int wm  = wid * 16;

    __shared__ alignas(16) __nv_bfloat16 sqh[64 * ASTRIDE], sql[64 * ASTRIDE];
    __shared__ alignas(16) __nv_bfloat16 skh[64 * ASTRIDE], skl[64 * ASTRIDE];
    __shared__ alignas(16) __nv_bfloat16 svh[32 * VSTRIDE], svl[32 * VSTRIDE]; // V^T [d][key]

    const float* qkv = g_qkv + (size_t)b * 64 * QKVCOLS + h * 32;

    // ---- load + normalize q (threads 0-63) / k (threads 64-127), split bf16
    {
        int r = tid & 63;
        const float4* p = (const float4*)(qkv + (size_t)r * QKVCOLS + (tid < 64 ? 0 : 384));
        float v[32];
        #pragma unroll
        for (int i = 0; i < 8; i++) {
            float4 t = p[i];
            v[i * 4 + 0] = t.x; v[i * 4 + 1] = t.y; v[i * 4 + 2] = t.z; v[i * 4 + 3] = t.w;
        }
        float ss = 0.0f;
        #pragma unroll
        for (int i = 0; i < 32; i++) ss = fmaf(v[i], v[i], ss);
        float sc = rsqrtf(fmaxf(ss, 1e-12f));
        if (tid < 64) sc *= __expf(fminf(lscale[h], MAX_LOGIT));
        uint32_t* rh = (uint32_t*)((tid < 64 ? sqh : skh) + r * ASTRIDE);
        uint32_t* rl = (uint32_t*)((tid < 64 ? sql : skl) + r * ASTRIDE);
        #pragma unroll
        for (int i = 0; i < 16; i++) {
            uint32_t hi, lo;
            splitpack(v[2 * i] * sc, v[2 * i + 1] * sc, hi, lo);
            rh[i] = hi; rl[i] = lo;
        }
    }
    // ---- load v (all threads), split bf16, store transposed [d][key]
    {
        int r = tid >> 1, dh = (tid & 1) * 16;
        const float4* p = (const float4*)(qkv + 768 + (size_t)r * QKVCOLS + dh);
        #pragma unroll
        for (int i = 0; i < 4; i++) {
            float4 t = p[i];
            float vv[4] = {t.x, t.y, t.z, t.w};
            #pragma unroll
            for (int j = 0; j < 4; j++) {
                int d = dh + i * 4 + j;
                __nv_bfloat16 hv = __float2bfloat16(vv[j]);
                svh[d * VSTRIDE + r] = hv;
                svl[d * VSTRIDE + r] = __float2bfloat16(vv[j] - __bfloat162float(hv));
            }
        }
    }
    __syncthreads();

    // ---- scores: c[8 key-frags][4], split-2 bf16 MMA
    float c[8][4];
    #pragma unroll
    for (int j = 0; j < 8; j++)
        #pragma unroll
        for (int l = 0; l < 4; l++) c[j][l] = 0.0f;

    const uint32_t a_off = ((wm + (lane & 15)) * ASTRIDE + (lane >> 4) * 8) * 2;
    const uint32_t b_off = (((lane & 7) + ((lane >> 4) << 3)) * ASTRIDE
                            + ((lane >> 3) & 1) * 8) * 2;

    uint32_t ah[2][4], al[2][4];
    ldm_x4(ah[0][0], ah[0][1], ah[0][2], ah[0][3], smem_u32(sqh) + a_off);
    ldm_x4(ah[1][0], ah[1][1], ah[1][2], ah[1][3], smem_u32(sqh) + a_off + 32);
    ldm_x4(al[0][0], al[0][1], al[0][2], al[0][3], smem_u32(sql) + a_off);
    ldm_x4(al[1][0], al[1][1], al[1][2], al[1][3], smem_u32(sql) + a_off + 32);

    #pragma unroll
    for (int kb = 0; kb < 4; kb++) {
        uint32_t bh[2][2][2], bl[2][2][2];   // [kk][nfrag][2]
        #pragma unroll
        for (int kk = 0; kk < 2; kk++) {
            uint32_t r0, r1, r2, r3;
            ldm_x4(r0, r1, r2, r3,
                   smem_u32(skh) + b_off + kb * (16 * ASTRIDE * 2) + kk * 32);
            bh[kk][0][0] = r0; bh[kk][0][1] = r1; bh[kk][1][0] = r2; bh[kk][1][1] = r3;
            ldm_x4(r0, r1, r2, r3,
                   smem_u32(skl) + b_off + kb * (16 * ASTRIDE * 2) + kk * 32);
            bl[kk][0][0] = r0; bl[kk][0][1] = r1; bl[kk][1][0] = r2; bl[kk][1][1] = r3;
        }
        #pragma unroll
        for (int nf = 0; nf < 2; nf++) {
            int n = kb * 2 + nf;
            #pragma unroll
            for (int kk = 0; kk < 2; kk++) {
                mma16816bf(c[n], ah[kk], bh[kk][nf][0], bh[kk][nf][1]);  // hi*hi
                mma16816bf(c[n], ah[kk], bl[kk][nf][0], bl[kk][nf][1]);  // hi*lo
                mma16816bf(c[n], al[kk], bh[kk][nf][0], bh[kk][nf][1]);  // lo*hi
            }
        }
    }

    // ---- add combined bias+mask
    {
        const float* bm = g_bm + ((size_t)h * 64 + (b & 63)) * 4096;
        #pragma unroll
        for (int j = 0; j < 8; j++) {
            int cb = j * 8 + tg * 2;
            float2 m0 = *(const float2*)(bm + (wm + g) * 64 + cb);
            float2 m1 = *(const float2*)(bm + (wm + g + 8) * 64 + cb);
            c[j][0] += m0.x; c[j][1] += m0.y; c[j][2] += m1.x; c[j][3] += m1.y;
        }
    }

    // ---- fragment softmax (rows wm+g and wm+g+8)
    {
        float m0 = -1e30f, m1 = -1e30f;
        #pragma unroll
        for (int j = 0; j < 8; j++) {
            m0 = fmaxf(m0, fmaxf(c[j][0], c[j][1]));
            m1 = fmaxf(m1, fmaxf(c[j][2], c[j][3]));
        }
        m0 = fmaxf(m0, __shfl_xor_sync(0xFFFFFFFF, m0, 1));
        m0 = fmaxf(m0, __shfl_xor_sync(0xFFFFFFFF, m0, 2));
        m1 = fmaxf(m1, __shfl_xor_sync(0xFFFFFFFF, m1, 1));
        m1 = fmaxf(m1, __shfl_xor_sync(0xFFFFFFFF, m1, 2));
        float s0 = 0.0f, s1 = 0.0f;
        #pragma unroll
        for (int j = 0; j < 8; j++) {
            c[j][0] = __expf(c[j][0] - m0); s0 += c[j][0];
            c[j][1] = __expf(c[j][1] - m0); s0 += c[j][1];
            c[j][2] = __expf(c[j][2] - m1); s1 += c[j][2];
            c[j][3] = __expf(c[j][3] - m1); s1 += c[j][3];
        }
        s0 += __shfl_xor_sync(0xFFFFFFFF, s0, 1);
        s0 += __shfl_xor_sync(0xFFFFFFFF, s0, 2);
        s1 += __shfl_xor_sync(0xFFFFFFFF, s1, 1);
        s1 += __shfl_xor_sync(0xFFFFFFFF, s1, 2);
        float i0 = 1.0f / s0, i1 = 1.0f / s1;
        #pragma unroll
        for (int j = 0; j < 8; j++) {
            c[j][0] *= i0; c[j][1] *= i0; c[j][2] *= i1; c[j][3] *= i1;
        }
    }

    // ---- pack P fragments (A-layout) with split-2
    uint32_t ph[4][4], pl[4][4];   // [kstep][4 regs]
    #pragma unroll
    for (int ks = 0; ks < 4; ks++) {
        int j0 = 2 * ks, j1 = 2 * ks + 1;
        splitpack(c[j0][0], c[j0][1], ph[ks][0], pl[ks][0]);
        splitpack(c[j0][2], c[j0][3], ph[ks][1], pl[ks][1]);
        splitpack(c[j1][0], c[j1][1], ph[ks][2], pl[ks][2]);
        splitpack(c[j1][2], c[j1][3], ph[ks][3], pl[ks][3]);
    }

    // ---- PV: o[4 d-frags][4]
    float o[4][4];
    #pragma unroll
    for (int n = 0; n < 4; n++)
        #pragma unroll
        for (int l = 0; l < 4; l++) o[n][l] = 0.0f;

    const uint32_t vb_off = (((lane & 7) + ((lane >> 4) << 3)) * VSTRIDE
                             + ((lane >> 3) & 1) * 8) * 2;
    #pragma unroll
    for (int ng = 0; ng < 2; ng++) {
        #pragma unroll
        for (int ks = 0; ks < 4; ks++) {
            uint32_t r0, r1, r2, r3, s0, s1, s2, s3;
            ldm_x4(r0, r1, r2, r3,
                   smem_u32(svh) + vb_off + ng * (16 * VSTRIDE * 2) + ks * 32);
            ldm_x4(s0, s1, s2, s3,
                   smem_u32(svl) + vb_off + ng * (16 * VSTRIDE * 2) + ks * 32);
            int n0i = ng * 2, n1i = ng * 2 + 1;
            mma16816bf(o[n0i], ph[ks], r0, r1);   // ph*vh
            mma16816bf(o[n0i], ph[ks], s0, s1);   // ph*vl
            mma16816bf(o[n0i], pl[ks], r0, r1);   // pl*vh
            mma16816bf(o[n1i], ph[ks], r2, r3);
            mma16816bf(o[n1i], ph[ks], s2, s3);
            mma16816bf(o[n1i], pl[ks], r2, r3);
        }
    }

    // ---- write fp16 ctx to g_a
    {
        __half* o0 = g_a + (size_t)(b * 64 + wm + g) * DIMF + h * 32;
        __half* o1 = o0 + (size_t)8 * DIMF;
        #pragma unroll
        for (int n = 0; n < 4; n++) {
            int col = n * 8 + tg * 2;
            *(__half2*)(o0 + col) = __floats2half2_rn(o[n][0], o[n][1]);
            *(__half2*)(o1 + col) = __floats2half2_rn(o[n][2], o[n][3]);
        }
    }
}

// ---------------------------------------------------------------------------
extern "C" void kernel_launch(void* const* d_in, const int* in_sizes, int n_in,
                              void* d_out, int out_size)
{
    const float* x           = (const float*)d_in[0];
    const float* mask        = (const float*)d_in[1];
    const float* qkv_w       = (const float*)d_in[2];
    const float* proj_w      = (const float*)d_in[3];
    const float* proj_b      = (const float*)d_in[4];
    const float* cpb_w1      = (const float*)d_in[5];
    const float* cpb_b1      = (const float*)d_in[6];
    const float* cpb_w2      = (const float*)d_in[7];
    const float* cpb_b2      = (const float*)d_in[8];
    const float* logit_scale = (const float*)d_in[9];
    const float* rpb_table   = (const float*)d_in[10];
    const int*   rpb_idx     = (const int*)d_in[11];
    float* out = (float*)d_out;

    float* qkv_ptr = nullptr;
    __half *a_ptr = nullptr, *wq_ptr = nullptr, *wp_ptr = nullptr;
    cudaGetSymbolAddress((void**)&qkv_ptr, g_qkv);
    cudaGetSymbolAddress((void**)&a_ptr,  g_a);
    cudaGetSymbolAddress((void**)&wq_ptr, g_wq);
    cudaGetSymbolAddress((void**)&wp_ptr, g_wp);

    // K0: CPB bias table + bias/mask combine + weight converts (tiny)
    rpb_kernel<<<1, 256>>>(rpb_table, cpb_w1, cpb_b1, cpb_w2, cpb_b2, rpb_idx);
    bm_kernel<<<NHEADS * 64, 256>>>(mask);
    conv_w<<<(DIMF * QKVCOLS + 255) / 256, 256>>>(qkv_w, wq_ptr, QKVCOLS);
    conv_w<<<(DIMF * DIMF + 255) / 256, 256>>>(proj_w, wp_ptr, DIMF);

    // convert activations for QKV GEMM
    conv_act<<<(int)(((size_t)MTOK * 96 + 255) / 256), 256>>>(x, a_ptr);

    // K1: QKV GEMM (65536 x 1152 x 384), fp16 HMMA
    gemm_hmma<<<dim3(QKVCOLS / 128, MTOK / 128), 256>>>(
        a_ptr, wq_ptr, nullptr, qkv_ptr, QKVCOLS, DIMF);

    // K2: attention per (head, window); tensor-core split-bf16; writes fp16 ctx
    attn_kernel<<<dim3(NHEADS, NWIN), 128>>>(logit_scale);

    // K3: projection (65536 x 384 x 384) + bias, fp16 HMMA
    gemm_hmma<<<dim3(DIMF / 128, MTOK / 128), 256>>>(
        a_ptr, wp_ptr, proj_b, out, DIMF, DIMF);
}